// round 16
// baseline (speedup 1.0000x reference)
#include <cuda_runtime.h>
#include <cstdint>

#define D 1024
#define MAX_B 32
#define CHUNK 8
#define NBX 32
#define EPS 1e-6f
#define TRUNC 1e-9f

// 16-byte alignment REQUIRED: accessed as float4.
__device__ __align__(16) float g_state[MAX_B * D];   // zero at load; self-cleaning
__device__ __align__(16) float g_pool[MAX_B * D];
__device__ int g_arrive[MAX_B];                      // zero at load; self-cleaning

__device__ __forceinline__ float warp_sum(float v) {
#pragma unroll
    for (int o = 16; o > 0; o >>= 1) v += __shfl_xor_sync(0xffffffffu, v, o);
    return v;
}

// ---- Kernel 1 (R15 scan, verbatim): truncated decay-weighted scan
//      + fused pool rmsnorm; chunk-0 loads hoisted above decay prologue ----
__global__ void scan_kernel(const float* __restrict__ x,
                            const float* __restrict__ logit,
                            const float* __restrict__ norm1_w,
                            const float* __restrict__ norm2_w, int S) {
    const int b = blockIdx.y;
    const int tid = threadIdx.x;    // 256
    const int d0 = tid * 4;
    const int wid = tid >> 5, lane = tid & 31;

    const int c0 = blockIdx.x;
    int t_hi0 = S - 1 - c0 * CHUNK;
    float4 xr[CHUNK];
    if (t_hi0 >= 0) {
        int t_lo = t_hi0 - (CHUNK - 1);
        if (t_lo < 0) t_lo = 0;
        const int valid0 = t_hi0 - t_lo + 1;
        const float* xb = x + ((size_t)b * S + t_hi0) * D + d0;
#pragma unroll
        for (int i = 0; i < CHUNK; i++)
            xr[i] = (i < valid0) ? *(const float4*)(xb - (size_t)i * D)
                                 : make_float4(0.f, 0.f, 0.f, 0.f);
    } else {
#pragma unroll
        for (int i = 0; i < CHUNK; i++) xr[i] = make_float4(0.f, 0.f, 0.f, 0.f);
    }

    const float4 lg = *(const float4*)&logit[d0];
    float4 dc4;
    dc4.x = 1.f / (1.f + __expf(-lg.x));
    dc4.y = 1.f / (1.f + __expf(-lg.y));
    dc4.z = 1.f / (1.f + __expf(-lg.z));
    dc4.w = 1.f / (1.f + __expf(-lg.w));

    __shared__ float smax[8];
    float m = fmaxf(fmaxf(dc4.x, dc4.y), fmaxf(dc4.z, dc4.w));
#pragma unroll
    for (int o = 16; o > 0; o >>= 1) m = fmaxf(m, __shfl_xor_sync(0xffffffffu, m, o));
    if (lane == 0) smax[wid] = m;
    __syncthreads();
    float maxd = fmaxf(fmaxf(smax[0], smax[1]), fmaxf(smax[2], smax[3]));
    maxd = fmaxf(maxd, fmaxf(fmaxf(smax[4], smax[5]), fmaxf(smax[6], smax[7])));

    const int sch = (S + CHUNK - 1) / CHUNK;
    int nch;
    if (maxd >= 0.9999995f) {
        nch = sch;
    } else {
        float K = logf(TRUNC) / logf(maxd);
        int Ki = (int)K + 2;
        nch = (Ki + CHUNK - 1) / CHUNK;
        if (nch > sch) nch = sch;
        if (nch < 1) nch = 1;
    }

    float4 acc = make_float4(0.f, 0.f, 0.f, 0.f);
    bool did = false;

    __shared__ float sred[CHUNK][8];
    __shared__ float srstd[CHUNK];

    for (int c = c0; c < nch; c += NBX) {
        did = true;
        const int t_hi = S - 1 - c * CHUNK;
        int t_lo = t_hi - (CHUNK - 1);
        if (t_lo < 0) t_lo = 0;
        const int valid = t_hi - t_lo + 1;
        const int e_min = c * CHUNK;

        if (c != c0) {
            const float* xb = x + ((size_t)b * S + t_hi) * D + d0;
#pragma unroll
            for (int i = 0; i < CHUNK; i++)
                xr[i] = (i < valid) ? *(const float4*)(xb - (size_t)i * D)
                                    : make_float4(0.f, 0.f, 0.f, 0.f);
        }

#pragma unroll
        for (int i = 0; i < CHUNK; i++) {
            float4 v = xr[i];
            float s = warp_sum(v.x * v.x + v.y * v.y + v.z * v.z + v.w * v.w);
            if (lane == 0) sred[i][wid] = s;
        }
        __syncthreads();
        if (tid < CHUNK) {
            float s = 0.f;
#pragma unroll
            for (int w = 0; w < 8; w++) s += sred[tid][w];
            srstd[tid] = rsqrtf(s * (1.f / D) + EPS);
        }
        __syncthreads();

        float4 w4;
        w4.x = __powf(dc4.x, (float)e_min);
        w4.y = __powf(dc4.y, (float)e_min);
        w4.z = __powf(dc4.z, (float)e_min);
        w4.w = __powf(dc4.w, (float)e_min);

#pragma unroll
        for (int i = 0; i < CHUNK; i++) {
            if (i < valid) {
                float r = srstd[i];
                acc.x += w4.x * xr[i].x * r;
                acc.y += w4.y * xr[i].y * r;
                acc.z += w4.z * xr[i].z * r;
                acc.w += w4.w * xr[i].w * r;
            }
            w4.x *= dc4.x; w4.y *= dc4.y; w4.z *= dc4.z; w4.w *= dc4.w;
        }
        __syncthreads();
    }

    float* gs = &g_state[b * D + d0];
    if (did) {
        const float4 nw = *(const float4*)&norm1_w[d0];
        atomicAdd(gs + 0, acc.x * nw.x * (1.f - dc4.x));
        atomicAdd(gs + 1, acc.y * nw.y * (1.f - dc4.y));
        atomicAdd(gs + 2, acc.z * nw.z * (1.f - dc4.z));
        atomicAdd(gs + 3, acc.w * nw.w * (1.f - dc4.w));
    }

    __threadfence();
    __shared__ int s_last;
    if (tid == 0)
        s_last = (atomicAdd(&g_arrive[b], 1) == NBX - 1);
    __syncthreads();
    if (!s_last) return;

    const float4 xl = *(const float4*)(x + ((size_t)b * S + (S - 1)) * D + d0);
    const float4 st = __ldcg((const float4*)gs);
    float4 v = make_float4(xl.x + st.x, xl.y + st.y, xl.z + st.z, xl.w + st.w);

    *(float4*)gs = make_float4(0.f, 0.f, 0.f, 0.f);
    if (tid == 0) g_arrive[b] = 0;

    float s = warp_sum(v.x * v.x + v.y * v.y + v.z * v.z + v.w * v.w);
    __shared__ float sm2[8];
    __shared__ float srs;
    if (lane == 0) sm2[wid] = s;
    __syncthreads();
    if (tid == 0) {
        float t = 0.f;
#pragma unroll
        for (int w = 0; w < 8; w++) t += sm2[w];
        srs = rsqrtf(t * (1.f / D) + EPS);
    }
    __syncthreads();

    const float r = srs;
    const float4 n2 = *(const float4*)&norm2_w[d0];
    float4 p = make_float4(v.x * r * n2.x, v.y * r * n2.y,
                           v.z * r * n2.z, v.w * r * n2.w);
    *(float4*)&g_pool[b * D + d0] = p;
}

// ---- Kernel 2: bulk-async GEMV. Each block DMAs its 32KB W tile
//      (8 contiguous rows) into smem via cp.async.bulk, grouping runs
//      under the copy, compute reads W from smem + pool via __ldg. ----
__global__ void gemm_kernel(const int* __restrict__ experts,
                            const float* __restrict__ W,
                            float* __restrict__ out, int B) {
    const int e = blockIdx.y;
    const int tid = threadIdx.x;   // 256
    const int warp = tid >> 5, lane = tid & 31;

    __shared__ __align__(128) float s_w[8 * D];    // 32 KB W tile
    __shared__ uint64_t s_mbar;
    __shared__ int s_exp[MAX_B];
    __shared__ int s_bl[MAX_B];
    __shared__ int s_nb;

    const uint32_t smem_w = (uint32_t)__cvta_generic_to_shared(s_w);
    const uint32_t mbar   = (uint32_t)__cvta_generic_to_shared(&s_mbar);

    if (tid == 0)
        asm volatile("mbarrier.init.shared.b64 [%0], %1;" :: "r"(mbar), "r"(1));
    if (tid < B) s_exp[tid] = experts[tid];
    __syncthreads();

    // issue the DMA: one 32KB contiguous bulk copy (rows row0..row0+7)
    if (tid == 0) {
        const int row0 = blockIdx.x * 8;
        const float* Wt = W + ((size_t)e * D + row0) * D;
        asm volatile(
            "mbarrier.arrive.expect_tx.shared.b64 _, [%0], %1;"
            :: "r"(mbar), "r"(32768u) : "memory");
        asm volatile(
            "cp.async.bulk.shared::cta.global.mbarrier::complete_tx::bytes "
            "[%0], [%1], %2, [%3];"
            :: "r"(smem_w), "l"(Wt), "r"(32768u), "r"(mbar) : "memory");
    }

    // expert grouping under the copy
    if (tid == 0) {
        int n = 0;
        for (int b = 0; b < B; b++)
            if (s_exp[b] == e) s_bl[n++] = b;
        s_nb = n;
    }
    __syncthreads();
    const int nb = s_nb;

    // wait for the W tile
    {
        unsigned done = 0;
        while (!done) {
            asm volatile(
                "{\n\t.reg .pred p;\n\t"
                "mbarrier.try_wait.parity.acquire.cta.shared::cta.b64 p, [%1], %2;\n\t"
                "selp.u32 %0, 1, 0, p;\n\t}"
                : "=r"(done) : "r"(mbar), "r"(0u) : "memory");
        }
    }
    __syncthreads();

    if (nb == 0) return;

    // W row for this warp from smem: 8 conflict-free LDS.128
    const float* wr = &s_w[warp * D];
    float4 w[8];
#pragma unroll
    for (int i = 0; i < 8; i++)
        w[i] = *(const float4*)(wr + i * 128 + lane * 4);

    const int row = blockIdx.x * 8 + warp;
    for (int j = 0; j < nb; j++) {
        const float* pb = &g_pool[s_bl[j] * D];
        float a = 0.f;
#pragma unroll
        for (int i = 0; i < 8; i++) {
            const float4 p = __ldg((const float4*)(pb + i * 128 + lane * 4));
            a += w[i].x * p.x + w[i].y * p.y + w[i].z * p.z + w[i].w * p.w;
        }
        float s = warp_sum(a);
        if (lane == 0) out[s_bl[j] * D + row] = fmaxf(s, 0.f);
    }
}

// ---- Launch ----
extern "C" void kernel_launch(void* const* d_in, const int* in_sizes, int n_in,
                              void* d_out, int out_size) {
    const float* x        = (const float*)d_in[0];
    const int*   experts  = (const int*)d_in[1];
    const float* norm1_w  = (const float*)d_in[2];
    const float* tdl      = (const float*)d_in[3];
    const float* norm2_w  = (const float*)d_in[4];
    const float* W        = (const float*)d_in[5];
    float* out = (float*)d_out;

    const int B = in_sizes[1];
    const int S = in_sizes[0] / (B * D);
    const int E = in_sizes[5] / (D * D);

    dim3 gscan(NBX, B);
    scan_kernel<<<gscan, 256>>>(x, tdl, norm1_w, norm2_w, S);

    dim3 ggemm(D / 8, E);
    gemm_kernel<<<ggemm, 256>>>(experts, W, out, B);
}